// round 2
// baseline (speedup 1.0000x reference)
#include <cuda_runtime.h>
#include <math.h>

#define Tn 512
#define Bn 64
#define Hn 512
#define G4 2048          // 4*H
#define REC_CTAS 148
#define CTAS_PER_DIR 74

// ---------------- scratch (device globals; no runtime allocation) ----------
__device__ float g_xg[2 * Tn * G4 * Bn];       // [dir][t][n][b]
__device__ float g_out0[Tn * Bn * 2 * Hn];     // layer0 output = layer1 input
__device__ float g_h[2][2][Hn][Bn];            // [buf][dir][j][b]
__device__ unsigned long long g_bar_count   = 0ULL;
__device__ unsigned long long g_bar_release = 0ULL;

// ---------------- software grid barrier (monotonic, graph-replay safe) -----
__device__ __forceinline__ void grid_barrier(unsigned long long* s_tgt)
{
    __syncthreads();
    if (threadIdx.x == 0) {
        __threadfence();
        unsigned long long tgt = *s_tgt;
        unsigned long long arr = atomicAdd(&g_bar_count, 1ULL) + 1ULL;
        if (arr == (unsigned long long)REC_CTAS * tgt) {
            atomicExch(&g_bar_release, tgt);
        } else {
            while (atomicAdd(&g_bar_release, 0ULL) < tgt) { __nanosleep(64); }
        }
        __threadfence();
        *s_tgt = tgt + 1ULL;
    }
    __syncthreads();
}

__device__ __forceinline__ float sigf(float x) { return 1.0f / (1.0f + __expf(-x)); }

// ---------------- input projection GEMM ------------------------------------
// g_xg[dir][t][n][b] = sum_k X[t][b][k] * W[n][k] + bih[n] + bhh[n]
__global__ __launch_bounds__(256, 2)
void input_gemm_kernel(const float* __restrict__ Xext,
                       const float* __restrict__ W,
                       const float* __restrict__ bih,
                       const float* __restrict__ bhh,
                       int K, int dir, int internal)
{
    __shared__ __align__(16) float Ws[32][128];   // [k][n]
    __shared__ __align__(16) float Xs[32][64];    // [k][b]

    const int t   = blockIdx.y;
    const int n0  = blockIdx.x * 128;
    const int tid = threadIdx.x;
    const int tn  = tid & 31;   // n-quad index (lane)
    const int bg  = tid >> 5;   // warp id = b-octet index

    const float* __restrict__ X  = internal ? g_out0 : Xext;
    const float* __restrict__ Xt = X + (size_t)t * Bn * K;

    float acc[4][8];
#pragma unroll
    for (int r = 0; r < 4; ++r)
#pragma unroll
        for (int c = 0; c < 8; ++c) acc[r][c] = 0.0f;

    for (int k0 = 0; k0 < K; k0 += 32) {
        __syncthreads();
#pragma unroll
        for (int i = 0; i < 4; ++i) {
            int idx = tid * 4 + i;
            int row = idx >> 3;
            int c4  = idx & 7;
            float4 w = *(const float4*)(W + (size_t)(n0 + row) * K + k0 + c4 * 4);
            Ws[c4 * 4 + 0][row] = w.x;
            Ws[c4 * 4 + 1][row] = w.y;
            Ws[c4 * 4 + 2][row] = w.z;
            Ws[c4 * 4 + 3][row] = w.w;
        }
#pragma unroll
        for (int i = 0; i < 2; ++i) {
            int idx = tid * 2 + i;
            int b   = idx >> 3;
            int c4  = idx & 7;
            float4 xv = *(const float4*)(Xt + (size_t)b * K + k0 + c4 * 4);
            Xs[c4 * 4 + 0][b] = xv.x;
            Xs[c4 * 4 + 1][b] = xv.y;
            Xs[c4 * 4 + 2][b] = xv.z;
            Xs[c4 * 4 + 3][b] = xv.w;
        }
        __syncthreads();
#pragma unroll
        for (int kk = 0; kk < 32; ++kk) {
            const float4 w  = *(const float4*)&Ws[kk][tn * 4];
            const float4 x0 = *(const float4*)&Xs[kk][bg * 8];
            const float4 x1 = *(const float4*)&Xs[kk][bg * 8 + 4];
            const float wr[4] = { w.x, w.y, w.z, w.w };
            const float xc[8] = { x0.x, x0.y, x0.z, x0.w, x1.x, x1.y, x1.z, x1.w };
#pragma unroll
            for (int r = 0; r < 4; ++r)
#pragma unroll
                for (int c = 0; c < 8; ++c)
                    acc[r][c] += wr[r] * xc[c];
        }
    }

    float* xgd = g_xg + (size_t)dir * Tn * G4 * Bn + ((size_t)t * G4 + n0) * Bn;
#pragma unroll
    for (int r = 0; r < 4; ++r) {
        int n = tn * 4 + r;
        float bias = bih[n0 + n] + bhh[n0 + n];
        float4 o0 = make_float4(acc[r][0] + bias, acc[r][1] + bias,
                                acc[r][2] + bias, acc[r][3] + bias);
        float4 o1 = make_float4(acc[r][4] + bias, acc[r][5] + bias,
                                acc[r][6] + bias, acc[r][7] + bias);
        *(float4*)(xgd + (size_t)n * Bn + bg * 8)     = o0;
        *(float4*)(xgd + (size_t)n * Bn + bg * 8 + 4) = o1;
    }
}

// ---------------- persistent recurrent kernel ------------------------------
__global__ __launch_bounds__(256, 1)
void lstm_rec_kernel(const float* __restrict__ whh_f,
                     const float* __restrict__ whh_b,
                     const float* __restrict__ mask,
                     float* __restrict__ outext,
                     int final_layer)
{
    __shared__ __align__(16) float hs[64][Bn];    // h chunk [k][b]
    __shared__ __align__(16) float Ws[28][64];    // W_hh rows [row][k]
    __shared__ __align__(16) float Gs[28][Bn];    // gate pre-activations
    __shared__ __align__(16) float cs[7][Bn];     // persistent cell state
    __shared__ __align__(16) float msk[Bn];
    __shared__ unsigned long long s_tgt;

    const int cta = blockIdx.x;
    const int tid = threadIdx.x;
    const int dir = (cta >= CTAS_PER_DIR) ? 1 : 0;
    const int c   = cta - dir * CTAS_PER_DIR;
    const int j0  = (c * Hn) / CTAS_PER_DIR;
    const int j1  = ((c + 1) * Hn) / CTAS_PER_DIR;
    const int nj  = j1 - j0;                 // 6 or 7
    const int nrows = 4 * nj;                // 24 or 28 gate rows

    const float* __restrict__ Whh = dir ? whh_b : whh_f;
    const float* __restrict__ xgd = g_xg + (size_t)dir * Tn * G4 * Bn;
    float* __restrict__ out = final_layer ? outext : g_out0;

    if (tid == 0) s_tgt = g_bar_release + 1ULL;

    {   // zero h read-buffer slice and cell state
        float* hz = &g_h[0][dir][j0][0];
        for (int i = tid; i < nj * Bn; i += 256) hz[i] = 0.0f;
        for (int i = tid; i < nj * Bn; i += 256) cs[i >> 6][i & 63] = 0.0f;
    }
    grid_barrier(&s_tgt);

    const int tn = tid >> 4;        // row-pair index (0..15)
    const int tb = tid & 15;        // b-quad index
    const int b0 = tb * 4;
    const int r0 = tn * 2;
    const bool active = (r0 + 1) < nrows + 1 && r0 < nrows;  // pairs fully inside (nrows even)
    int ng0 = 0, ng1 = 0;
    if (active) {
        int g0  = r0 / nj,        jj0 = r0 - g0 * nj;
        int g1  = (r0 + 1) / nj,  jj1 = (r0 + 1) - g1 * nj;
        ng0 = g0 * Hn + j0 + jj0;
        ng1 = g1 * Hn + j0 + jj1;
    }

    for (int s = 0; s < Tn; ++s) {
        const int t  = dir ? (Tn - 1 - s) : s;
        const int rb = s & 1;

        if (tid < 16)
            ((float4*)msk)[tid] = ((const float4*)(mask + (size_t)t * Bn))[tid];

        float acc0[4] = {0, 0, 0, 0}, acc1[4] = {0, 0, 0, 0};
        if (active) {
            const float4 a0 = *(const float4*)(xgd + ((size_t)t * G4 + ng0) * Bn + b0);
            const float4 a1 = *(const float4*)(xgd + ((size_t)t * G4 + ng1) * Bn + b0);
            acc0[0] = a0.x; acc0[1] = a0.y; acc0[2] = a0.z; acc0[3] = a0.w;
            acc1[0] = a1.x; acc1[1] = a1.y; acc1[2] = a1.z; acc1[3] = a1.w;
        }

        for (int k0 = 0; k0 < Hn; k0 += 64) {
            __syncthreads();
            const float4* hsrc = (const float4*)(&g_h[rb][dir][k0][0]);
#pragma unroll
            for (int i = 0; i < 4; ++i)
                ((float4*)hs)[tid + i * 256] = hsrc[tid + i * 256];
            for (int idx = tid; idx < nrows * 16; idx += 256) {
                int r  = idx >> 4;
                int c4 = idx & 15;
                int g  = r / nj;
                int jj = r - g * nj;
                int n  = g * Hn + j0 + jj;
                *(((float4*)&Ws[r][0]) + c4) =
                    *(const float4*)(Whh + (size_t)n * Hn + k0 + c4 * 4);
            }
            __syncthreads();
            if (active) {
#pragma unroll
                for (int k4 = 0; k4 < 16; ++k4) {
                    const float4 w0 = *(const float4*)&Ws[r0][k4 * 4];
                    const float4 w1 = *(const float4*)&Ws[r0 + 1][k4 * 4];
                    const float4 ha = *(const float4*)&hs[k4 * 4 + 0][b0];
                    const float4 hb = *(const float4*)&hs[k4 * 4 + 1][b0];
                    const float4 hc = *(const float4*)&hs[k4 * 4 + 2][b0];
                    const float4 hd = *(const float4*)&hs[k4 * 4 + 3][b0];
                    acc0[0] += w0.x * ha.x + w0.y * hb.x + w0.z * hc.x + w0.w * hd.x;
                    acc0[1] += w0.x * ha.y + w0.y * hb.y + w0.z * hc.y + w0.w * hd.y;
                    acc0[2] += w0.x * ha.z + w0.y * hb.z + w0.z * hc.z + w0.w * hd.z;
                    acc0[3] += w0.x * ha.w + w0.y * hb.w + w0.z * hc.w + w0.w * hd.w;
                    acc1[0] += w1.x * ha.x + w1.y * hb.x + w1.z * hc.x + w1.w * hd.x;
                    acc1[1] += w1.x * ha.y + w1.y * hb.y + w1.z * hc.y + w1.w * hd.y;
                    acc1[2] += w1.x * ha.z + w1.y * hb.z + w1.z * hc.z + w1.w * hd.z;
                    acc1[3] += w1.x * ha.w + w1.y * hb.w + w1.z * hc.w + w1.w * hd.w;
                }
            }
        }

        if (active) {
            *(float4*)&Gs[r0][b0]     = make_float4(acc0[0], acc0[1], acc0[2], acc0[3]);
            *(float4*)&Gs[r0 + 1][b0] = make_float4(acc1[0], acc1[1], acc1[2], acc1[3]);
        }
        __syncthreads();

        for (int p = tid; p < nj * Bn; p += 256) {
            const int jj = p >> 6;
            const int b  = p & 63;
            const float gi = Gs[jj][b];
            const float gf = Gs[nj + jj][b];
            const float gg = Gs[2 * nj + jj][b];
            const float go = Gs[3 * nj + jj][b];
            const float ii = sigf(gi);
            const float ff = sigf(gf);
            const float gv = tanhf(gg);
            const float oo = sigf(go);
            float cc = ff * cs[jj][b] + ii * gv;
            float hh = oo * tanhf(cc);
            const float m = msk[b];
            hh *= m;
            cc *= m;
            cs[jj][b] = cc;
            g_h[rb ^ 1][dir][j0 + jj][b] = hh;
            out[((size_t)t * Bn + b) * (2 * Hn) + (size_t)dir * Hn + (j0 + jj)] = hh;
        }
        grid_barrier(&s_tgt);
    }
}

// ---------------- launch ----------------------------------------------------
extern "C" void kernel_launch(void* const* d_in, const int* in_sizes, int n_in,
                              void* d_out, int out_size)
{
    const float* x      = (const float*)d_in[0];
    const float* mask   = (const float*)d_in[1];
    const float* f_wih0 = (const float*)d_in[2];
    const float* f_whh0 = (const float*)d_in[3];
    const float* f_bih0 = (const float*)d_in[4];
    const float* f_bhh0 = (const float*)d_in[5];
    const float* b_wih0 = (const float*)d_in[6];
    const float* b_whh0 = (const float*)d_in[7];
    const float* b_bih0 = (const float*)d_in[8];
    const float* b_bhh0 = (const float*)d_in[9];
    const float* f_wih1 = (const float*)d_in[10];
    const float* f_whh1 = (const float*)d_in[11];
    const float* f_bih1 = (const float*)d_in[12];
    const float* f_bhh1 = (const float*)d_in[13];
    const float* b_wih1 = (const float*)d_in[14];
    const float* b_whh1 = (const float*)d_in[15];
    const float* b_bih1 = (const float*)d_in[16];
    const float* b_bhh1 = (const float*)d_in[17];
    float* out = (float*)d_out;

    dim3 ggrid(G4 / 128, Tn);

    // ---- layer 0 ----
    input_gemm_kernel<<<ggrid, 256>>>(x, f_wih0, f_bih0, f_bhh0, 512, 0, 0);
    input_gemm_kernel<<<ggrid, 256>>>(x, b_wih0, b_bih0, b_bhh0, 512, 1, 0);
    lstm_rec_kernel<<<REC_CTAS, 256>>>(f_whh0, b_whh0, mask, out, 0);

    // ---- layer 1 (input = g_out0, K = 1024) ----
    input_gemm_kernel<<<ggrid, 256>>>(x, f_wih1, f_bih1, f_bhh1, 1024, 0, 1);
    input_gemm_kernel<<<ggrid, 256>>>(x, b_wih1, b_bih1, b_bhh1, 1024, 1, 1);
    lstm_rec_kernel<<<REC_CTAS, 256>>>(f_whh1, b_whh1, mask, out, 1);
}

// round 5
// speedup vs baseline: 1.2867x; 1.2867x over previous
#include <cuda_runtime.h>
#include <math.h>
#include <stdint.h>

#define Tn 512
#define Bn 64
#define Hn 512
#define G4 2048
#define REC_CTAS 148
#define CTAS_PER_DIR 74

__device__ float g_xg[2ULL * Tn * G4 * Bn];    // [dir][t][gate][b]
__device__ float g_out0[(size_t)Tn * Bn * 2 * Hn];
__device__ float g_h[2][2][Hn][Bn];
__device__ unsigned long long g_bar_count   = 0ULL;
__device__ unsigned long long g_bar_release = 0ULL;

__device__ __forceinline__ float tf32r(float x) {
    float y; asm("cvt.rna.tf32.f32 %0, %1;" : "=f"(y) : "f"(x)); return y;
}
__device__ __forceinline__ void mma8(float* c, const uint32_t* a, uint32_t b0, uint32_t b1) {
    asm volatile("mma.sync.aligned.m16n8k8.row.col.f32.tf32.tf32.f32 "
        "{%0,%1,%2,%3}, {%4,%5,%6,%7}, {%8,%9}, {%0,%1,%2,%3};\n"
        : "+f"(c[0]), "+f"(c[1]), "+f"(c[2]), "+f"(c[3])
        : "r"(a[0]), "r"(a[1]), "r"(a[2]), "r"(a[3]), "r"(b0), "r"(b1));
}
__device__ __forceinline__ float sigf(float x) { return 1.0f / (1.0f + __expf(-x)); }

__device__ __forceinline__ void grid_barrier(unsigned long long* s_tgt)
{
    __syncthreads();
    if (threadIdx.x == 0) {
        __threadfence();
        unsigned long long tgt = *s_tgt;
        unsigned long long arr = atomicAdd(&g_bar_count, 1ULL) + 1ULL;
        if (arr == (unsigned long long)REC_CTAS * tgt) {
            atomicExch(&g_bar_release, tgt);
        } else {
            while (atomicAdd(&g_bar_release, 0ULL) < tgt) { __nanosleep(64); }
        }
        __threadfence();
        *s_tgt = tgt + 1ULL;
    }
    __syncthreads();
}

// -------- input GEMM on tensor cores (mma.sync tf32) ------------------------
// out[m=gate][n=batch] = sum_k W[m][k] * X[t][n][k] + bias.  A=W tf32, B=x hi/lo split.
// smem: As[2][128][36], Bs[2][64][36] (fp32, stride 36 -> conflict-free frags)
#define ASTR 36
#define A_CH (128 * ASTR)
#define B_CH (64 * ASTR)
#define IN_SMEM ((2 * A_CH + 2 * B_CH) * 4)

__global__ __launch_bounds__(256, 2)
void input_gemm_mma(const float* __restrict__ W, const float* __restrict__ Xext,
                    const float* __restrict__ bih, const float* __restrict__ bhh,
                    int K, int dir, int internal)
{
    extern __shared__ float sm[];
    float* As = sm;                 // 2 bufs
    float* Bs = sm + 2 * A_CH;
    __shared__ float sbias[128];

    const int t = blockIdx.y, n0 = blockIdx.x * 128;
    const int tid = threadIdx.x, wid = tid >> 5, lane = tid & 31;
    const int gid = lane >> 2, tg = lane & 3;
    const int wm = wid >> 1, wn = wid & 1;
    const int NC = K >> 5;
    const float* __restrict__ X = internal ? g_out0 : Xext;
    const float* __restrict__ Xt = X + (size_t)t * Bn * K;

    if (tid < 128) sbias[tid] = bih[n0 + tid] + bhh[n0 + tid];

    float4 wr[4], xr[2];
    float acc[2][4][4];
#pragma unroll
    for (int a = 0; a < 2; ++a)
#pragma unroll
        for (int b = 0; b < 4; ++b)
#pragma unroll
            for (int c = 0; c < 4; ++c) acc[a][b][c] = 0.f;

    auto ldc = [&](int s) {
        const int k0 = s * 32;
#pragma unroll
        for (int i = 0; i < 4; ++i) {
            int idx = tid + i * 256, r = idx >> 3, c = idx & 7;
            wr[i] = *(const float4*)(W + (size_t)(n0 + r) * K + k0 + c * 4);
        }
#pragma unroll
        for (int i = 0; i < 2; ++i) {
            int idx = tid + i * 256, r = idx >> 3, c = idx & 7;
            xr[i] = *(const float4*)(Xt + (size_t)r * K + k0 + c * 4);
        }
    };
    auto stc = [&](int p) {
        float* A = As + p * A_CH;
        float* B = Bs + p * B_CH;
#pragma unroll
        for (int i = 0; i < 4; ++i) {
            int idx = tid + i * 256, r = idx >> 3, c = idx & 7;
            float4 v = wr[i];
            v.x = tf32r(v.x); v.y = tf32r(v.y); v.z = tf32r(v.z); v.w = tf32r(v.w);
            *(float4*)(A + r * ASTR + c * 4) = v;
        }
#pragma unroll
        for (int i = 0; i < 2; ++i) {
            int idx = tid + i * 256, r = idx >> 3, c = idx & 7;
            *(float4*)(B + r * ASTR + c * 4) = xr[i];
        }
    };

    ldc(0); stc(0); __syncthreads();

    for (int s = 0; s < NC; ++s) {
        const int p = s & 1;
        if (s + 1 < NC) ldc(s + 1);
        const float* A = As + p * A_CH;
        const float* B = Bs + p * B_CH;
#pragma unroll
        for (int ks = 0; ks < 4; ++ks) {
            const int kk = ks * 8;
            uint32_t a[2][4];
#pragma unroll
            for (int mt = 0; mt < 2; ++mt) {
                int r = wm * 32 + mt * 16 + gid;
                a[mt][0] = __float_as_uint(A[r * ASTR + kk + tg]);
                a[mt][1] = __float_as_uint(A[(r + 8) * ASTR + kk + tg]);
                a[mt][2] = __float_as_uint(A[r * ASTR + kk + tg + 4]);
                a[mt][3] = __float_as_uint(A[(r + 8) * ASTR + kk + tg + 4]);
            }
#pragma unroll
            for (int nt = 0; nt < 4; ++nt) {
                int col = wn * 32 + nt * 8 + gid;
                float v0 = B[col * ASTR + kk + tg];
                float v1 = B[col * ASTR + kk + tg + 4];
                float h0 = tf32r(v0), h1 = tf32r(v1);
                uint32_t l0 = __float_as_uint(tf32r(v0 - h0));
                uint32_t l1 = __float_as_uint(tf32r(v1 - h1));
#pragma unroll
                for (int mt = 0; mt < 2; ++mt) {
                    mma8(acc[mt][nt], a[mt], __float_as_uint(h0), __float_as_uint(h1));
                    mma8(acc[mt][nt], a[mt], l0, l1);
                }
            }
        }
        __syncthreads();
        if (s + 1 < NC) { stc(1 - p); __syncthreads(); }
    }

    float* xgd = g_xg + (size_t)dir * Tn * G4 * Bn + (size_t)t * G4 * Bn;
#pragma unroll
    for (int mt = 0; mt < 2; ++mt) {
#pragma unroll
        for (int half = 0; half < 2; ++half) {
            int m = wm * 32 + mt * 16 + gid + half * 8;
            float bias = sbias[m];
            float* row = xgd + (size_t)(n0 + m) * Bn;
#pragma unroll
            for (int nt = 0; nt < 4; ++nt) {
                int b = wn * 32 + nt * 8 + 2 * tg;
                float2 v = make_float2(acc[mt][nt][2 * half] + bias,
                                       acc[mt][nt][2 * half + 1] + bias);
                *(float2*)(row + b) = v;
            }
        }
    }
}

// -------- persistent recurrent kernel (unchanged from R2 pass) --------------
__global__ __launch_bounds__(256, 1)
void lstm_rec_kernel(const float* __restrict__ whh_f, const float* __restrict__ whh_b,
                     const float* __restrict__ mask, float* __restrict__ outext,
                     int final_layer)
{
    __shared__ __align__(16) float hs[64][Bn];
    __shared__ __align__(16) float Ws[28][64];
    __shared__ __align__(16) float Gs[28][Bn];
    __shared__ __align__(16) float cs[7][Bn];
    __shared__ __align__(16) float msk[Bn];
    __shared__ unsigned long long s_tgt;

    const int cta = blockIdx.x, tid = threadIdx.x;
    const int dir = (cta >= CTAS_PER_DIR) ? 1 : 0;
    const int c = cta - dir * CTAS_PER_DIR;
    const int j0 = (c * Hn) / CTAS_PER_DIR;
    const int j1 = ((c + 1) * Hn) / CTAS_PER_DIR;
    const int nj = j1 - j0, nrows = 4 * nj;

    const float* __restrict__ Whh = dir ? whh_b : whh_f;
    const float* __restrict__ xgd = g_xg + (size_t)dir * Tn * G4 * Bn;
    float* __restrict__ out = final_layer ? outext : g_out0;

    if (tid == 0) s_tgt = g_bar_release + 1ULL;
    {
        float* hz = &g_h[0][dir][j0][0];
        for (int i = tid; i < nj * Bn; i += 256) hz[i] = 0.0f;
        for (int i = tid; i < nj * Bn; i += 256) cs[i >> 6][i & 63] = 0.0f;
    }
    grid_barrier(&s_tgt);

    const int tn = tid >> 4, tb = tid & 15;
    const int b0 = tb * 4, r0 = tn * 2;
    const bool active = r0 < nrows;
    int ng0 = 0, ng1 = 0;
    if (active) {
        int g0 = r0 / nj, jj0 = r0 - g0 * nj;
        int g1 = (r0 + 1) / nj, jj1 = (r0 + 1) - g1 * nj;
        ng0 = g0 * Hn + j0 + jj0;
        ng1 = g1 * Hn + j0 + jj1;
    }

    for (int s = 0; s < Tn; ++s) {
        const int t = dir ? (Tn - 1 - s) : s;
        const int rb = s & 1;
        if (tid < 16)
            ((float4*)msk)[tid] = ((const float4*)(mask + (size_t)t * Bn))[tid];

        float acc0[4] = {0, 0, 0, 0}, acc1[4] = {0, 0, 0, 0};
        if (active) {
            const float4 a0 = *(const float4*)(xgd + ((size_t)t * G4 + ng0) * Bn + b0);
            const float4 a1 = *(const float4*)(xgd + ((size_t)t * G4 + ng1) * Bn + b0);
            acc0[0] = a0.x; acc0[1] = a0.y; acc0[2] = a0.z; acc0[3] = a0.w;
            acc1[0] = a1.x; acc1[1] = a1.y; acc1[2] = a1.z; acc1[3] = a1.w;
        }

        for (int k0 = 0; k0 < Hn; k0 += 64) {
            __syncthreads();
            const float4* hsrc = (const float4*)(&g_h[rb][dir][k0][0]);
#pragma unroll
            for (int i = 0; i < 4; ++i)
                ((float4*)hs)[tid + i * 256] = hsrc[tid + i * 256];
            for (int idx = tid; idx < nrows * 16; idx += 256) {
                int r = idx >> 4, c4 = idx & 15;
                int g = r / nj, jj = r - g * nj;
                int n = g * Hn + j0 + jj;
                *(((float4*)&Ws[r][0]) + c4) =
                    *(const float4*)(Whh + (size_t)n * Hn + k0 + c4 * 4);
            }
            __syncthreads();
            if (active) {
#pragma unroll
                for (int k4 = 0; k4 < 16; ++k4) {
                    const float4 w0 = *(const float4*)&Ws[r0][k4 * 4];
                    const float4 w1 = *(const float4*)&Ws[r0 + 1][k4 * 4];
                    const float4 ha = *(const float4*)&hs[k4 * 4 + 0][b0];
                    const float4 hb = *(const float4*)&hs[k4 * 4 + 1][b0];
                    const float4 hc = *(const float4*)&hs[k4 * 4 + 2][b0];
                    const float4 hd = *(const float4*)&hs[k4 * 4 + 3][b0];
                    acc0[0] += w0.x * ha.x + w0.y * hb.x + w0.z * hc.x + w0.w * hd.x;
                    acc0[1] += w0.x * ha.y + w0.y * hb.y + w0.z * hc.y + w0.w * hd.y;
                    acc0[2] += w0.x * ha.z + w0.y * hb.z + w0.z * hc.z + w0.w * hd.z;
                    acc0[3] += w0.x * ha.w + w0.y * hb.w + w0.z * hc.w + w0.w * hd.w;
                    acc1[0] += w1.x * ha.x + w1.y * hb.x + w1.z * hc.x + w1.w * hd.x;
                    acc1[1] += w1.x * ha.y + w1.y * hb.y + w1.z * hc.y + w1.w * hd.y;
                    acc1[2] += w1.x * ha.z + w1.y * hb.z + w1.z * hc.z + w1.w * hd.z;
                    acc1[3] += w1.x * ha.w + w1.y * hb.w + w1.z * hc.w + w1.w * hd.w;
                }
            }
        }

        if (active) {
            *(float4*)&Gs[r0][b0]     = make_float4(acc0[0], acc0[1], acc0[2], acc0[3]);
            *(float4*)&Gs[r0 + 1][b0] = make_float4(acc1[0], acc1[1], acc1[2], acc1[3]);
        }
        __syncthreads();

        for (int p = tid; p < nj * Bn; p += 256) {
            const int jj = p >> 6, b = p & 63;
            const float ii = sigf(Gs[jj][b]);
            const float ff = sigf(Gs[nj + jj][b]);
            const float gv = tanhf(Gs[2 * nj + jj][b]);
            const float oo = sigf(Gs[3 * nj + jj][b]);
            float cc = ff * cs[jj][b] + ii * gv;
            float hh = oo * tanhf(cc);
            const float m = msk[b];
            hh *= m; cc *= m;
            cs[jj][b] = cc;
            g_h[rb ^ 1][dir][j0 + jj][b] = hh;
            out[((size_t)t * Bn + b) * (2 * Hn) + (size_t)dir * Hn + (j0 + jj)] = hh;
        }
        grid_barrier(&s_tgt);
    }
}

extern "C" void kernel_launch(void* const* d_in, const int* in_sizes, int n_in,
                              void* d_out, int out_size)
{
    const float* x      = (const float*)d_in[0];
    const float* mask   = (const float*)d_in[1];
    const float* f_wih0 = (const float*)d_in[2];
    const float* f_whh0 = (const float*)d_in[3];
    const float* f_bih0 = (const float*)d_in[4];
    const float* f_bhh0 = (const float*)d_in[5];
    const float* b_wih0 = (const float*)d_in[6];
    const float* b_whh0 = (const float*)d_in[7];
    const float* b_bih0 = (const float*)d_in[8];
    const float* b_bhh0 = (const float*)d_in[9];
    const float* f_wih1 = (const float*)d_in[10];
    const float* f_whh1 = (const float*)d_in[11];
    const float* f_bih1 = (const float*)d_in[12];
    const float* f_bhh1 = (const float*)d_in[13];
    const float* b_wih1 = (const float*)d_in[14];
    const float* b_whh1 = (const float*)d_in[15];
    const float* b_bih1 = (const float*)d_in[16];
    const float* b_bhh1 = (const float*)d_in[17];
    float* out = (float*)d_out;

    cudaFuncSetAttribute(input_gemm_mma,
                         cudaFuncAttributeMaxDynamicSharedMemorySize, IN_SMEM);

    dim3 g(G4 / 128, Tn);
    input_gemm_mma<<<g, 256, IN_SMEM>>>(f_wih0, x, f_bih0, f_bhh0, 512, 0, 0);
    input_gemm_mma<<<g, 256, IN_SMEM>>>(b_wih0, x, b_bih0, b_bhh0, 512, 1, 0);
    lstm_rec_kernel<<<REC_CTAS, 256>>>(f_whh0, b_whh0, mask, out, 0);

    input_gemm_mma<<<g, 256, IN_SMEM>>>(f_wih1, x, f_bih1, f_bhh1, 1024, 0, 1);
    input_gemm_mma<<<g, 256, IN_SMEM>>>(b_wih1, x, b_bih1, b_bhh1, 1024, 1, 1);
    lstm_rec_kernel<<<REC_CTAS, 256>>>(f_whh1, b_whh1, mask, out, 1);
}

// round 6
// speedup vs baseline: 2.3954x; 1.8617x over previous
#include <cuda_runtime.h>
#include <cuda_bf16.h>
#include <math.h>
#include <stdint.h>

#define Tn 512
#define Bn 64
#define Hn 512
#define G4 2048
#define REC_CTAS 128

__device__ float    g_xg[2ULL * Tn * G4 * Bn];     // [dir][t][gate_row][b]
__device__ float    g_out0[(size_t)Tn * Bn * 2 * Hn];
__device__ uint32_t g_hhi[2][2][256][64];          // [buf][dir][jpair][b] packed bf16 hi
__device__ uint32_t g_hlo[2][2][256][64];          // lo plane
__device__ unsigned long long g_bar_count   = 0ULL;
__device__ unsigned long long g_bar_release = 0ULL;

__device__ __forceinline__ float tf32r(float x) {
    float y; asm("cvt.rna.tf32.f32 %0, %1;" : "=f"(y) : "f"(x)); return y;
}
__device__ __forceinline__ void mma8(float* c, const uint32_t* a, uint32_t b0, uint32_t b1) {
    asm volatile("mma.sync.aligned.m16n8k8.row.col.f32.tf32.tf32.f32 "
        "{%0,%1,%2,%3}, {%4,%5,%6,%7}, {%8,%9}, {%0,%1,%2,%3};\n"
        : "+f"(c[0]), "+f"(c[1]), "+f"(c[2]), "+f"(c[3])
        : "r"(a[0]), "r"(a[1]), "r"(a[2]), "r"(a[3]), "r"(b0), "r"(b1));
}
__device__ __forceinline__ void mma16(float* c, const uint32_t* a, uint32_t b0, uint32_t b1) {
    asm volatile("mma.sync.aligned.m16n8k16.row.col.f32.bf16.bf16.f32 "
        "{%0,%1,%2,%3}, {%4,%5,%6,%7}, {%8,%9}, {%0,%1,%2,%3};\n"
        : "+f"(c[0]), "+f"(c[1]), "+f"(c[2]), "+f"(c[3])
        : "r"(a[0]), "r"(a[1]), "r"(a[2]), "r"(a[3]), "r"(b0), "r"(b1));
}
__device__ __forceinline__ uint32_t packbf(float a, float b) {
    __nv_bfloat16 x = __float2bfloat16_rn(a), y = __float2bfloat16_rn(b);
    return ((uint32_t)__bfloat16_as_ushort(y) << 16) | __bfloat16_as_ushort(x);
}
__device__ __forceinline__ float sigf(float x) { return 1.0f / (1.0f + __expf(-x)); }

__device__ __forceinline__ void grid_barrier(unsigned long long* s_tgt)
{
    __syncthreads();
    if (threadIdx.x == 0) {
        __threadfence();
        unsigned long long tgt = *s_tgt;
        unsigned long long arr = atomicAdd(&g_bar_count, 1ULL) + 1ULL;
        if (arr == (unsigned long long)REC_CTAS * tgt) {
            atomicExch(&g_bar_release, tgt);
        } else {
            while (atomicAdd(&g_bar_release, 0ULL) < tgt) { __nanosleep(64); }
        }
        __threadfence();
        *s_tgt = tgt + 1ULL;
    }
    __syncthreads();
}

// -------- input GEMM (unchanged from R5 pass) --------------------------------
#define ASTR 36
#define A_CH (128 * ASTR)
#define B_CH (64 * ASTR)
#define IN_SMEM ((2 * A_CH + 2 * B_CH) * 4)

__global__ __launch_bounds__(256, 2)
void input_gemm_mma(const float* __restrict__ W, const float* __restrict__ Xext,
                    const float* __restrict__ bih, const float* __restrict__ bhh,
                    int K, int dir, int internal)
{
    extern __shared__ float sm[];
    float* As = sm;
    float* Bs = sm + 2 * A_CH;
    __shared__ float sbias[128];

    const int t = blockIdx.y, n0 = blockIdx.x * 128;
    const int tid = threadIdx.x, wid = tid >> 5, lane = tid & 31;
    const int gid = lane >> 2, tg = lane & 3;
    const int wm = wid >> 1, wn = wid & 1;
    const int NC = K >> 5;
    const float* __restrict__ X = internal ? g_out0 : Xext;
    const float* __restrict__ Xt = X + (size_t)t * Bn * K;

    if (tid < 128) sbias[tid] = bih[n0 + tid] + bhh[n0 + tid];

    float4 wr[4], xr[2];
    float acc[2][4][4];
#pragma unroll
    for (int a = 0; a < 2; ++a)
#pragma unroll
        for (int b = 0; b < 4; ++b)
#pragma unroll
            for (int c = 0; c < 4; ++c) acc[a][b][c] = 0.f;

    auto ldc = [&](int s) {
        const int k0 = s * 32;
#pragma unroll
        for (int i = 0; i < 4; ++i) {
            int idx = tid + i * 256, r = idx >> 3, c = idx & 7;
            wr[i] = *(const float4*)(W + (size_t)(n0 + r) * K + k0 + c * 4);
        }
#pragma unroll
        for (int i = 0; i < 2; ++i) {
            int idx = tid + i * 256, r = idx >> 3, c = idx & 7;
            xr[i] = *(const float4*)(Xt + (size_t)r * K + k0 + c * 4);
        }
    };
    auto stc = [&](int p) {
        float* A = As + p * A_CH;
        float* B = Bs + p * B_CH;
#pragma unroll
        for (int i = 0; i < 4; ++i) {
            int idx = tid + i * 256, r = idx >> 3, c = idx & 7;
            float4 v = wr[i];
            v.x = tf32r(v.x); v.y = tf32r(v.y); v.z = tf32r(v.z); v.w = tf32r(v.w);
            *(float4*)(A + r * ASTR + c * 4) = v;
        }
#pragma unroll
        for (int i = 0; i < 2; ++i) {
            int idx = tid + i * 256, r = idx >> 3, c = idx & 7;
            *(float4*)(B + r * ASTR + c * 4) = xr[i];
        }
    };

    ldc(0); stc(0); __syncthreads();

    for (int s = 0; s < NC; ++s) {
        const int p = s & 1;
        if (s + 1 < NC) ldc(s + 1);
        const float* A = As + p * A_CH;
        const float* B = Bs + p * B_CH;
#pragma unroll
        for (int ks = 0; ks < 4; ++ks) {
            const int kk = ks * 8;
            uint32_t a[2][4];
#pragma unroll
            for (int mt = 0; mt < 2; ++mt) {
                int r = wm * 32 + mt * 16 + gid;
                a[mt][0] = __float_as_uint(A[r * ASTR + kk + tg]);
                a[mt][1] = __float_as_uint(A[(r + 8) * ASTR + kk + tg]);
                a[mt][2] = __float_as_uint(A[r * ASTR + kk + tg + 4]);
                a[mt][3] = __float_as_uint(A[(r + 8) * ASTR + kk + tg + 4]);
            }
#pragma unroll
            for (int nt = 0; nt < 4; ++nt) {
                int col = wn * 32 + nt * 8 + gid;
                float v0 = B[col * ASTR + kk + tg];
                float v1 = B[col * ASTR + kk + tg + 4];
                float h0 = tf32r(v0), h1 = tf32r(v1);
                uint32_t l0 = __float_as_uint(tf32r(v0 - h0));
                uint32_t l1 = __float_as_uint(tf32r(v1 - h1));
#pragma unroll
                for (int mt = 0; mt < 2; ++mt) {
                    mma8(acc[mt][nt], a[mt], __float_as_uint(h0), __float_as_uint(h1));
                    mma8(acc[mt][nt], a[mt], l0, l1);
                }
            }
        }
        __syncthreads();
        if (s + 1 < NC) { stc(1 - p); __syncthreads(); }
    }

    float* xgd = g_xg + (size_t)dir * Tn * G4 * Bn + (size_t)t * G4 * Bn;
#pragma unroll
    for (int mt = 0; mt < 2; ++mt) {
#pragma unroll
        for (int half = 0; half < 2; ++half) {
            int m = wm * 32 + mt * 16 + gid + half * 8;
            float bias = sbias[m];
            float* row = xgd + (size_t)(n0 + m) * Bn;
#pragma unroll
            for (int nt = 0; nt < 4; ++nt) {
                int b = wn * 32 + nt * 8 + 2 * tg;
                *(float2*)(row + b) = make_float2(acc[mt][nt][2 * half] + bias,
                                                  acc[mt][nt][2 * half + 1] + bias);
            }
        }
    }
}

// -------- recurrent kernel on tensor cores (bf16x3) --------------------------
// 128 CTAs; CTA = dir, 8 j's (rows: 4 gates x 8 j = 32), batch 64, K=512.
// W_hh slice resident in smem as bf16 hi/lo pair-planes; h double-buffered
// global pair-planes written by the epilogue itself.
#define WHI_OFF 0
#define WLO_OFF 8320
#define BHI_OFF 16640
#define BLO_OFF 25856
#define GS_OFF  35072
#define CS_OFF  37184
#define MSK_OFF 37696
#define REC_SMEM (37760 * 4)

__global__ __launch_bounds__(256, 1)
void lstm_rec_mma(const float* __restrict__ whh_f, const float* __restrict__ whh_b,
                  const float* __restrict__ mask, float* __restrict__ outext,
                  int final_layer)
{
    extern __shared__ uint32_t smw[];
    uint32_t* Whi = smw + WHI_OFF;      // [32][260]
    uint32_t* Wlo = smw + WLO_OFF;
    uint32_t* Bhi = smw + BHI_OFF;      // [2][64][72]
    uint32_t* Blo = smw + BLO_OFF;
    float*    Gs  = (float*)(smw + GS_OFF);   // [32][66]
    float*    cs  = (float*)(smw + CS_OFF);   // [8][64]
    float*    msk = (float*)(smw + MSK_OFF);
    __shared__ unsigned long long s_tgt;

    const int cta = blockIdx.x, tid = threadIdx.x;
    const int dir = cta >> 6;
    const int j0  = (cta & 63) * 8;
    const int lane = tid & 31, wid = tid >> 5;
    const int gid = lane >> 2, tg = lane & 3;
    const int wm = wid >> 2, wn = wid & 3;     // 2 x 4 warp grid
    const int colb = wn * 16;

    const float* __restrict__ Whh = dir ? whh_b : whh_f;
    const float* __restrict__ xgd = g_xg + (size_t)dir * Tn * G4 * Bn;
    float* __restrict__ out = final_layer ? outext : g_out0;

    if (tid == 0) s_tgt = g_bar_release + 1ULL;

    // pack W_hh slice: row r <-> gate r>>3, j j0+(r&7); 256 k-pairs
    for (int i = tid; i < 8192; i += 256) {
        int r = i >> 8, p = i & 255;
        int grow = (r >> 3) * Hn + j0 + (r & 7);
        float2 w = *(const float2*)(Whh + (size_t)grow * Hn + 2 * p);
        float hx = __bfloat162float(__float2bfloat16_rn(w.x));
        float hy = __bfloat162float(__float2bfloat16_rn(w.y));
        Whi[r * 260 + p] = packbf(w.x, w.y);
        Wlo[r * 260 + p] = packbf(w.x - hx, w.y - hy);
    }
    // zero h read-buffer 0 (this CTA's 4 pairs) and cell state
    {
        int p = tid >> 6, b = tid & 63;
        g_hhi[0][dir][(j0 >> 1) + p][b] = 0u;
        g_hlo[0][dir][(j0 >> 1) + p][b] = 0u;
    }
    for (int i = tid; i < 512; i += 256) cs[i] = 0.0f;
    grid_barrier(&s_tgt);

    for (int s = 0; s < Tn; ++s) {
        const int t  = dir ? (Tn - 1 - s) : s;
        const int rb = s & 1;
        if (tid < 16)
            ((float4*)msk)[tid] = ((const float4*)(mask + (size_t)t * Bn))[tid];

        // init accumulators from xg preacts
        float c0[2][4];
        {
            const size_t xb = (size_t)t * G4 * Bn;
            const int jlo = j0 + gid;
            const float* p0 = xgd + xb + ((size_t)(2 * wm) * Hn + jlo) * Bn;
            const float* p1 = xgd + xb + ((size_t)(2 * wm + 1) * Hn + jlo) * Bn;
#pragma unroll
            for (int nt = 0; nt < 2; ++nt) {
                int col = colb + nt * 8 + 2 * tg;
                float2 u = *(const float2*)(p0 + col);
                float2 v = *(const float2*)(p1 + col);
                c0[nt][0] = u.x; c0[nt][1] = u.y; c0[nt][2] = v.x; c0[nt][3] = v.y;
            }
        }

        const uint32_t* srcHi = &g_hhi[rb][dir][0][0];
        const uint32_t* srcLo = &g_hlo[rb][dir][0][0];

        // stage chunk 0 (k-pairs 0..63)
#pragma unroll
        for (int i = 0; i < 4; ++i) {
            int idx = tid + i * 256, q = idx >> 4, c4 = (idx & 15) * 4;
            *(uint4*)(Bhi + q * 72 + c4) = *(const uint4*)(srcHi + q * 64 + c4);
            *(uint4*)(Blo + q * 72 + c4) = *(const uint4*)(srcLo + q * 64 + c4);
        }
        __syncthreads();

        uint4 ph[4], pl[4];
        for (int ch = 0; ch < 4; ++ch) {
            const int buf = ch & 1;
            const uint32_t* BH = Bhi + buf * 4608;
            const uint32_t* BL = Blo + buf * 4608;
            if (ch < 3) {
#pragma unroll
                for (int i = 0; i < 4; ++i) {
                    int idx = tid + i * 256, q = idx >> 4, c4 = (idx & 15) * 4;
                    ph[i] = *(const uint4*)(srcHi + ((ch + 1) * 64 + q) * 64 + c4);
                    pl[i] = *(const uint4*)(srcLo + ((ch + 1) * 64 + q) * 64 + c4);
                }
            }
#pragma unroll
            for (int kt = 0; kt < 8; ++kt) {
                const int qb = kt * 8;
                const int ra = wm * 16 + gid;
                const int kp = ch * 64 + qb + tg;
                uint32_t ahi[4], alo[4];
                ahi[0] = Whi[ra * 260 + kp];       ahi[1] = Whi[(ra + 8) * 260 + kp];
                ahi[2] = Whi[ra * 260 + kp + 4];   ahi[3] = Whi[(ra + 8) * 260 + kp + 4];
                alo[0] = Wlo[ra * 260 + kp];       alo[1] = Wlo[(ra + 8) * 260 + kp];
                alo[2] = Wlo[ra * 260 + kp + 4];   alo[3] = Wlo[(ra + 8) * 260 + kp + 4];
#pragma unroll
                for (int nt = 0; nt < 2; ++nt) {
                    const int col = colb + nt * 8 + gid;
                    uint32_t bh0 = BH[(qb + tg) * 72 + col];
                    uint32_t bh1 = BH[(qb + tg + 4) * 72 + col];
                    uint32_t bl0 = BL[(qb + tg) * 72 + col];
                    uint32_t bl1 = BL[(qb + tg + 4) * 72 + col];
                    mma16(c0[nt], ahi, bh0, bh1);
                    mma16(c0[nt], ahi, bl0, bl1);
                    mma16(c0[nt], alo, bh0, bh1);
                }
            }
            __syncthreads();
            if (ch < 3) {
                uint32_t* B2H = Bhi + (buf ^ 1) * 4608;
                uint32_t* B2L = Blo + (buf ^ 1) * 4608;
#pragma unroll
                for (int i = 0; i < 4; ++i) {
                    int idx = tid + i * 256, q = idx >> 4, c4 = (idx & 15) * 4;
                    *(uint4*)(B2H + q * 72 + c4) = ph[i];
                    *(uint4*)(B2L + q * 72 + c4) = pl[i];
                }
                __syncthreads();
            }
        }

        // frags -> Gs
#pragma unroll
        for (int nt = 0; nt < 2; ++nt) {
            int col = colb + nt * 8 + 2 * tg;
            int r = wm * 16 + gid;
            *(float2*)&Gs[r * 66 + col]       = make_float2(c0[nt][0], c0[nt][1]);
            *(float2*)&Gs[(r + 8) * 66 + col] = make_float2(c0[nt][2], c0[nt][3]);
        }
        __syncthreads();

        // cell update: thread owns j-pair (2jp, 2jp+1) x one batch column
        {
            const int jp = tid >> 6, b = tid & 63;
            const float m = msk[b];
            float hv[2];
#pragma unroll
            for (int e = 0; e < 2; ++e) {
                const int jl = 2 * jp + e;
                const float ii = sigf(Gs[jl * 66 + b]);
                const float ff = sigf(Gs[(8 + jl) * 66 + b]);
                const float gv = tanhf(Gs[(16 + jl) * 66 + b]);
                const float oo = sigf(Gs[(24 + jl) * 66 + b]);
                float ccv = ff * cs[jl * 64 + b] + ii * gv;
                float hh = oo * tanhf(ccv);
                hh *= m; ccv *= m;
                cs[jl * 64 + b] = ccv;
                hv[e] = hh;
            }
            *(float2*)(out + ((size_t)t * Bn + b) * (2 * Hn) + (size_t)dir * Hn + j0 + 2 * jp)
                = make_float2(hv[0], hv[1]);
            float h0r = __bfloat162float(__float2bfloat16_rn(hv[0]));
            float h1r = __bfloat162float(__float2bfloat16_rn(hv[1]));
            const int pg = (j0 >> 1) + jp;
            g_hhi[rb ^ 1][dir][pg][b] = packbf(hv[0], hv[1]);
            g_hlo[rb ^ 1][dir][pg][b] = packbf(hv[0] - h0r, hv[1] - h1r);
        }
        grid_barrier(&s_tgt);
    }
}

extern "C" void kernel_launch(void* const* d_in, const int* in_sizes, int n_in,
                              void* d_out, int out_size)
{
    const float* x      = (const float*)d_in[0];
    const float* mask   = (const float*)d_in[1];
    const float* f_wih0 = (const float*)d_in[2];
    const float* f_whh0 = (const float*)d_in[3];
    const float* f_bih0 = (const float*)d_in[4];
    const float* f_bhh0 = (const float*)d_in[5];
    const float* b_wih0 = (const float*)d_in[6];
    const float* b_whh0 = (const float*)d_in[7];
    const float* b_bih0 = (const float*)d_in[8];
    const float* b_bhh0 = (const float*)d_in[9];
    const float* f_wih1 = (const float*)d_in[10];
    const float* f_whh1 = (const float*)d_in[11];
    const float* f_bih1 = (const float*)d_in[12];
    const float* f_bhh1 = (const float*)d_in[13];
    const float* b_wih1 = (const float*)d_in[14];
    const float* b_whh1 = (const float*)d_in[15];
    const float* b_bih1 = (const float*)d_in[16];
    const float* b_bhh1 = (const float*)d_in[17];
    float* out = (float*)d_out;

    cudaFuncSetAttribute(input_gemm_mma,
                         cudaFuncAttributeMaxDynamicSharedMemorySize, IN_SMEM);
    cudaFuncSetAttribute(lstm_rec_mma,
                         cudaFuncAttributeMaxDynamicSharedMemorySize, REC_SMEM);

    dim3 g(G4 / 128, Tn);
    input_gemm_mma<<<g, 256, IN_SMEM>>>(f_wih0, x, f_bih0, f_bhh0, 512, 0, 0);
    input_gemm_mma<<<g, 256, IN_SMEM>>>(b_wih0, x, b_bih0, b_bhh0, 512, 1, 0);
    lstm_rec_mma<<<REC_CTAS, 256, REC_SMEM>>>(f_whh0, b_whh0, mask, out, 0);

    input_gemm_mma<<<g, 256, IN_SMEM>>>(f_wih1, x, f_bih1, f_bhh1, 1024, 0, 1);
    input_gemm_mma<<<g, 256, IN_SMEM>>>(b_wih1, x, b_bih1, b_bhh1, 1024, 1, 1);
    lstm_rec_mma<<<REC_CTAS, 256, REC_SMEM>>>(f_whh1, b_whh1, mask, out, 1);
}

// round 7
// speedup vs baseline: 2.5490x; 1.0641x over previous
#include <cuda_runtime.h>
#include <cuda_bf16.h>
#include <math.h>
#include <stdint.h>

#define Tn 512
#define Bn 64
#define Hn 512
#define G4 2048
#define REC_CTAS 128

__device__ float    g_xg[2ULL * Tn * G4 * Bn];       // [dir][t][gate_row][b]
__device__ uint32_t g_xphi[(size_t)Tn * 512 * 64];   // [t][kpair][b]
__device__ uint32_t g_xplo[(size_t)Tn * 512 * 64];
__device__ uint32_t g_wphi[3145728];                 // packed W_ih planes
__device__ uint32_t g_wplo[3145728];
__device__ uint32_t g_hhi[2][2][256][64];            // [buf][dir][jpair][b]
__device__ uint32_t g_hlo[2][2][256][64];
__device__ unsigned long long g_bar_count2[2]   = {0ULL, 0ULL};
__device__ unsigned long long g_bar_release2[2] = {0ULL, 0ULL};

__device__ __forceinline__ void mma16(float* c, const uint32_t* a, uint32_t b0, uint32_t b1) {
    asm volatile("mma.sync.aligned.m16n8k16.row.col.f32.bf16.bf16.f32 "
        "{%0,%1,%2,%3}, {%4,%5,%6,%7}, {%8,%9}, {%0,%1,%2,%3};\n"
        : "+f"(c[0]), "+f"(c[1]), "+f"(c[2]), "+f"(c[3])
        : "r"(a[0]), "r"(a[1]), "r"(a[2]), "r"(a[3]), "r"(b0), "r"(b1));
}
__device__ __forceinline__ uint32_t packbf(float a, float b) {
    __nv_bfloat16 x = __float2bfloat16_rn(a), y = __float2bfloat16_rn(b);
    return ((uint32_t)__bfloat16_as_ushort(y) << 16) | __bfloat16_as_ushort(x);
}
__device__ __forceinline__ float bfr(float v) {
    return __bfloat162float(__float2bfloat16_rn(v));
}
__device__ __forceinline__ float sigf(float x) { return 1.0f / (1.0f + __expf(-x)); }

__device__ __forceinline__ void dir_barrier(unsigned long long* s_tgt, int dir)
{
    __syncthreads();
    if (threadIdx.x == 0) {
        __threadfence();
        unsigned long long tgt = *s_tgt;
        unsigned long long arr = atomicAdd(&g_bar_count2[dir], 1ULL) + 1ULL;
        if (arr == 64ULL * tgt) {
            atomicExch(&g_bar_release2[dir], tgt);
        } else {
            while (atomicAdd(&g_bar_release2[dir], 0ULL) < tgt) { __nanosleep(64); }
        }
        __threadfence();
        *s_tgt = tgt + 1ULL;
    }
    __syncthreads();
}

// ---- pack W_ih: [rows][K] fp32 -> planes [row][kpair] -----------------------
__global__ void pack_w(const float* __restrict__ W, uint32_t* __restrict__ hi,
                       uint32_t* __restrict__ lo)
{
    size_t idx = (size_t)blockIdx.x * 256 + threadIdx.x;
    float2 w = *(const float2*)(W + 2 * idx);
    hi[idx] = packbf(w.x, w.y);
    lo[idx] = packbf(w.x - bfr(w.x), w.y - bfr(w.y));
}

// ---- pack x: [t][b][k] -> planes [t][kpair][b] ------------------------------
__global__ __launch_bounds__(256, 4) void pack_x(const float* __restrict__ x)
{
    __shared__ float smx[64 * 68];
    const int t = blockIdx.x, tid = threadIdx.x;
    for (int kb = 0; kb < 512; kb += 64) {
        __syncthreads();
#pragma unroll
        for (int i = 0; i < 4; ++i) {
            int idx = tid + i * 256, b = idx >> 4, f = idx & 15;
            float4 v = *(const float4*)(x + ((size_t)t * 64 + b) * 512 + kb + 4 * f);
            *(float4*)(smx + b * 68 + 4 * f) = v;
        }
        __syncthreads();
#pragma unroll
        for (int i = 0; i < 8; ++i) {
            int idx = tid + i * 256, kp = idx >> 6, b = idx & 63;
            float v0 = smx[b * 68 + 2 * kp], v1 = smx[b * 68 + 2 * kp + 1];
            size_t o = ((size_t)t * 512 + (kb >> 1) + kp) * 64 + b;
            g_xphi[o] = packbf(v0, v1);
            g_xplo[o] = packbf(v0 - bfr(v0), v1 - bfr(v1));
        }
    }
}

// ---- input GEMM: bf16x3, prepacked A and B ---------------------------------
// smem u32: AH[2][2560] AL[2][2560] BH[2][1152] BL[2][1152]
#define AST 20
#define IN_SMEM (14848 * 4)

__global__ __launch_bounds__(256, 2)
void input_gemm_mma(const uint32_t* __restrict__ Whi, const uint32_t* __restrict__ Wlo,
                    const float* __restrict__ bih, const float* __restrict__ bhh,
                    int KP, int dir)
{
    extern __shared__ uint32_t sm[];
    uint32_t *AH = sm, *AL = sm + 5120, *BH = sm + 10240, *BL = sm + 12544;
    __shared__ float sbias[128];

    const int t = blockIdx.y, n0 = blockIdx.x * 128;
    const int tid = threadIdx.x, wid = tid >> 5, lane = tid & 31;
    const int gid = lane >> 2, tg = lane & 3;
    const int wm = wid >> 1, wn = wid & 1;
    const int NC = KP >> 4;

    if (tid < 128) sbias[tid] = bih[n0 + tid] + bhh[n0 + tid];
    const uint32_t* XH = g_xphi + (size_t)t * 512 * 64;
    const uint32_t* XL = g_xplo + (size_t)t * 512 * 64;

    uint4 ar[4], br[2];
    float acc[2][4][4];
#pragma unroll
    for (int a = 0; a < 2; ++a)
#pragma unroll
        for (int b = 0; b < 4; ++b)
#pragma unroll
            for (int c = 0; c < 4; ++c) acc[a][b][c] = 0.f;

    auto ldc = [&](int s) {
        const int k0 = s * 16;
#pragma unroll
        for (int i = 0; i < 4; ++i) {
            int j = tid + (i & 1) * 256, r = j >> 2, c = j & 3;
            const uint32_t* src = (i >> 1) ? Wlo : Whi;
            ar[i] = *(const uint4*)(src + (size_t)(n0 + r) * KP + k0 + 4 * c);
        }
#pragma unroll
        for (int i = 0; i < 2; ++i) {
            int r = tid >> 4, c = tid & 15;
            const uint32_t* src = i ? XL : XH;
            br[i] = *(const uint4*)(src + (size_t)(k0 + r) * 64 + 4 * c);
        }
    };
    auto stc = [&](int p) {
#pragma unroll
        for (int i = 0; i < 4; ++i) {
            int j = tid + (i & 1) * 256, r = j >> 2, c = j & 3;
            uint32_t* dst = (i >> 1) ? AL : AH;
            *(uint4*)(dst + p * 2560 + r * AST + 4 * c) = ar[i];
        }
#pragma unroll
        for (int i = 0; i < 2; ++i) {
            int r = tid >> 4, c = tid & 15;
            uint32_t* dst = i ? BL : BH;
            *(uint4*)(dst + p * 1152 + r * 72 + 4 * c) = br[i];
        }
    };

    ldc(0); stc(0); __syncthreads();

    for (int s = 0; s < NC; ++s) {
        const int p = s & 1;
        if (s + 1 < NC) ldc(s + 1);
        const uint32_t* Ah = AH + p * 2560;
        const uint32_t* Al = AL + p * 2560;
        const uint32_t* Bh = BH + p * 1152;
        const uint32_t* Bl = BL + p * 1152;
#pragma unroll
        for (int ks = 0; ks < 2; ++ks) {
            const int kb = ks * 8;
            uint32_t ahi[2][4], alo[2][4];
#pragma unroll
            for (int mt = 0; mt < 2; ++mt) {
                int r = wm * 32 + mt * 16 + gid;
                ahi[mt][0] = Ah[r * AST + kb + tg];
                ahi[mt][1] = Ah[(r + 8) * AST + kb + tg];
                ahi[mt][2] = Ah[r * AST + kb + tg + 4];
                ahi[mt][3] = Ah[(r + 8) * AST + kb + tg + 4];
                alo[mt][0] = Al[r * AST + kb + tg];
                alo[mt][1] = Al[(r + 8) * AST + kb + tg];
                alo[mt][2] = Al[r * AST + kb + tg + 4];
                alo[mt][3] = Al[(r + 8) * AST + kb + tg + 4];
            }
#pragma unroll
            for (int nt = 0; nt < 4; ++nt) {
                int col = wn * 32 + nt * 8 + gid;
                uint32_t bh0 = Bh[(kb + tg) * 72 + col];
                uint32_t bh1 = Bh[(kb + tg + 4) * 72 + col];
                uint32_t bl0 = Bl[(kb + tg) * 72 + col];
                uint32_t bl1 = Bl[(kb + tg + 4) * 72 + col];
#pragma unroll
                for (int mt = 0; mt < 2; ++mt) {
                    mma16(acc[mt][nt], ahi[mt], bh0, bh1);
                    mma16(acc[mt][nt], ahi[mt], bl0, bl1);
                    mma16(acc[mt][nt], alo[mt], bh0, bh1);
                }
            }
        }
        __syncthreads();
        if (s + 1 < NC) { stc(1 - p); __syncthreads(); }
    }

    float* xgd = g_xg + (size_t)dir * Tn * G4 * Bn + (size_t)t * G4 * Bn;
#pragma unroll
    for (int mt = 0; mt < 2; ++mt) {
#pragma unroll
        for (int half = 0; half < 2; ++half) {
            int m = wm * 32 + mt * 16 + gid + half * 8;
            float bias = sbias[m];
            float* row = xgd + (size_t)(n0 + m) * Bn;
#pragma unroll
            for (int nt = 0; nt < 4; ++nt) {
                int b = wn * 32 + nt * 8 + 2 * tg;
                *(float2*)(row + b) = make_float2(acc[mt][nt][2 * half] + bias,
                                                  acc[mt][nt][2 * half + 1] + bias);
            }
        }
    }
}

// ---- recurrent kernel (bf16x3 mma, per-dir barrier, packed epilogue) -------
#define WHI_OFF 0
#define WLO_OFF 8320
#define BHI_OFF 16640
#define BLO_OFF 25856
#define GS_OFF  35072
#define CS_OFF  37184
#define MSK_OFF 37696
#define REC_SMEM (37760 * 4)

__global__ __launch_bounds__(256, 1)
void lstm_rec_mma(const float* __restrict__ whh_f, const float* __restrict__ whh_b,
                  const float* __restrict__ mask, float* __restrict__ outext,
                  int final_layer)
{
    extern __shared__ uint32_t smw[];
    uint32_t* Whi = smw + WHI_OFF;
    uint32_t* Wlo = smw + WLO_OFF;
    uint32_t* Bhi = smw + BHI_OFF;
    uint32_t* Blo = smw + BLO_OFF;
    float*    Gs  = (float*)(smw + GS_OFF);
    float*    cs  = (float*)(smw + CS_OFF);
    float*    msk = (float*)(smw + MSK_OFF);
    __shared__ unsigned long long s_tgt;

    const int cta = blockIdx.x, tid = threadIdx.x;
    const int dir = cta >> 6;
    const int j0  = (cta & 63) * 8;
    const int lane = tid & 31, wid = tid >> 5;
    const int gid = lane >> 2, tg = lane & 3;
    const int wm = wid >> 2, wn = wid & 3;
    const int colb = wn * 16;

    const float* __restrict__ Whh = dir ? whh_b : whh_f;
    const float* __restrict__ xgd = g_xg + (size_t)dir * Tn * G4 * Bn;

    if (tid == 0) s_tgt = g_bar_release2[dir] + 1ULL;

    for (int i = tid; i < 8192; i += 256) {
        int r = i >> 8, p = i & 255;
        int grow = (r >> 3) * Hn + j0 + (r & 7);
        float2 w = *(const float2*)(Whh + (size_t)grow * Hn + 2 * p);
        Whi[r * 260 + p] = packbf(w.x, w.y);
        Wlo[r * 260 + p] = packbf(w.x - bfr(w.x), w.y - bfr(w.y));
    }
    {
        int p = tid >> 6, b = tid & 63;
        g_hhi[0][dir][(j0 >> 1) + p][b] = 0u;
        g_hlo[0][dir][(j0 >> 1) + p][b] = 0u;
    }
    for (int i = tid; i < 512; i += 256) cs[i] = 0.0f;
    dir_barrier(&s_tgt, dir);

    for (int s = 0; s < Tn; ++s) {
        const int t  = dir ? (Tn - 1 - s) : s;
        const int rb = s & 1;
        if (tid < 16)
            ((float4*)msk)[tid] = ((const float4*)(mask + (size_t)t * Bn))[tid];

        float c0[2][4];
        {
            const size_t xb = (size_t)t * G4 * Bn;
            const int jlo = j0 + gid;
            const float* p0 = xgd + xb + ((size_t)(2 * wm) * Hn + jlo) * Bn;
            const float* p1 = xgd + xb + ((size_t)(2 * wm + 1) * Hn + jlo) * Bn;
#pragma unroll
            for (int nt = 0; nt < 2; ++nt) {
                int col = colb + nt * 8 + 2 * tg;
                float2 u = *(const float2*)(p0 + col);
                float2 v = *(const float2*)(p1 + col);
                c0[nt][0] = u.x; c0[nt][1] = u.y; c0[nt][2] = v.x; c0[nt][3] = v.y;
            }
        }

        const uint32_t* srcHi = &g_hhi[rb][dir][0][0];
        const uint32_t* srcLo = &g_hlo[rb][dir][0][0];
#pragma unroll
        for (int i = 0; i < 4; ++i) {
            int idx = tid + i * 256, q = idx >> 4, c4 = (idx & 15) * 4;
            *(uint4*)(Bhi + q * 72 + c4) = *(const uint4*)(srcHi + q * 64 + c4);
            *(uint4*)(Blo + q * 72 + c4) = *(const uint4*)(srcLo + q * 64 + c4);
        }
        __syncthreads();

        uint4 ph[4], pl[4];
        for (int ch = 0; ch < 4; ++ch) {
            const int buf = ch & 1;
            const uint32_t* BH = Bhi + buf * 4608;
            const uint32_t* BL = Blo + buf * 4608;
            if (ch < 3) {
#pragma unroll
                for (int i = 0; i < 4; ++i) {
                    int idx = tid + i * 256, q = idx >> 4, c4 = (idx & 15) * 4;
                    ph[i] = *(const uint4*)(srcHi + ((ch + 1) * 64 + q) * 64 + c4);
                    pl[i] = *(const uint4*)(srcLo + ((ch + 1) * 64 + q) * 64 + c4);
                }
            }
#pragma unroll
            for (int kt = 0; kt < 8; ++kt) {
                const int qb = kt * 8;
                const int ra = wm * 16 + gid;
                const int kp = ch * 64 + qb + tg;
                uint32_t ahi[4], alo[4];
                ahi[0] = Whi[ra * 260 + kp];       ahi[1] = Whi[(ra + 8) * 260 + kp];
                ahi[2] = Whi[ra * 260 + kp + 4];   ahi[3] = Whi[(ra + 8) * 260 + kp + 4];
                alo[0] = Wlo[ra * 260 + kp];       alo[1] = Wlo[(ra + 8) * 260 + kp];
                alo[2] = Wlo[ra * 260 + kp + 4];   alo[3] = Wlo[(ra + 8) * 260 + kp + 4];
#pragma unroll
                for (int nt = 0; nt < 2; ++nt) {
                    const int col = colb + nt * 8 + gid;
                    uint32_t bh0 = BH[(qb + tg) * 72 + col];
                    uint32_t bh1 = BH[(qb + tg + 4) * 72 + col];
                    uint32_t bl0 = BL[(qb + tg) * 72 + col];
                    uint32_t bl1 = BL[(qb + tg + 4) * 72 + col];
                    mma16(c0[nt], ahi, bh0, bh1);
                    mma16(c0[nt], ahi, bl0, bl1);
                    mma16(c0[nt], alo, bh0, bh1);
                }
            }
            __syncthreads();
            if (ch < 3) {
                uint32_t* B2H = Bhi + (buf ^ 1) * 4608;
                uint32_t* B2L = Blo + (buf ^ 1) * 4608;
#pragma unroll
                for (int i = 0; i < 4; ++i) {
                    int idx = tid + i * 256, q = idx >> 4, c4 = (idx & 15) * 4;
                    *(uint4*)(B2H + q * 72 + c4) = ph[i];
                    *(uint4*)(B2L + q * 72 + c4) = pl[i];
                }
                __syncthreads();
            }
        }

#pragma unroll
        for (int nt = 0; nt < 2; ++nt) {
            int col = colb + nt * 8 + 2 * tg;
            int r = wm * 16 + gid;
            *(float2*)&Gs[r * 66 + col]       = make_float2(c0[nt][0], c0[nt][1]);
            *(float2*)&Gs[(r + 8) * 66 + col] = make_float2(c0[nt][2], c0[nt][3]);
        }
        __syncthreads();

        {
            const int jp = tid >> 6, b = tid & 63;
            const float m = msk[b];
            float hv[2];
#pragma unroll
            for (int e = 0; e < 2; ++e) {
                const int jl = 2 * jp + e;
                const float ii = sigf(Gs[jl * 66 + b]);
                const float ff = sigf(Gs[(8 + jl) * 66 + b]);
                const float gv = tanhf(Gs[(16 + jl) * 66 + b]);
                const float oo = sigf(Gs[(24 + jl) * 66 + b]);
                float ccv = ff * cs[jl * 64 + b] + ii * gv;
                float hh = oo * tanhf(ccv);
                hh *= m; ccv *= m;
                cs[jl * 64 + b] = ccv;
                hv[e] = hh;
            }
            const int pg = (j0 >> 1) + jp;
            uint32_t phh = packbf(hv[0], hv[1]);
            uint32_t pll = packbf(hv[0] - bfr(hv[0]), hv[1] - bfr(hv[1]));
            g_hhi[rb ^ 1][dir][pg][b] = phh;
            g_hlo[rb ^ 1][dir][pg][b] = pll;
            if (final_layer) {
                *(float2*)(outext + ((size_t)t * Bn + b) * (2 * Hn)
                           + (size_t)dir * Hn + j0 + 2 * jp) = make_float2(hv[0], hv[1]);
            } else {
                size_t o = ((size_t)t * 512 + (size_t)dir * 256 + pg) * 64 + b;
                g_xphi[o] = phh;
                g_xplo[o] = pll;
            }
        }
        dir_barrier(&s_tgt, dir);
    }
}

extern "C" void kernel_launch(void* const* d_in, const int* in_sizes, int n_in,
                              void* d_out, int out_size)
{
    const float* x      = (const float*)d_in[0];
    const float* mask   = (const float*)d_in[1];
    const float* f_wih0 = (const float*)d_in[2];
    const float* f_whh0 = (const float*)d_in[3];
    const float* f_bih0 = (const float*)d_in[4];
    const float* f_bhh0 = (const float*)d_in[5];
    const float* b_wih0 = (const float*)d_in[6];
    const float* b_whh0 = (const float*)d_in[7];
    const float* b_bih0 = (const float*)d_in[8];
    const float* b_bhh0 = (const float*)d_in[9];
    const float* f_wih1 = (const float*)d_in[10];
    const float* f_whh1 = (const float*)d_in[11];
    const float* f_bih1 = (const float*)d_in[12];
    const float* f_bhh1 = (const float*)d_in[13];
    const float* b_wih1 = (const float*)d_in[14];
    const float* b_whh1 = (const float*)d_in[15];
    const float* b_bih1 = (const float*)d_in[16];
    const float* b_bhh1 = (const float*)d_in[17];
    float* out = (float*)d_out;

    cudaFuncSetAttribute(input_gemm_mma,
                         cudaFuncAttributeMaxDynamicSharedMemorySize, IN_SMEM);
    cudaFuncSetAttribute(lstm_rec_mma,
                         cudaFuncAttributeMaxDynamicSharedMemorySize, REC_SMEM);

    uint32_t* whi = nullptr; uint32_t* wlo = nullptr;
    cudaGetSymbolAddress((void**)&whi, g_wphi);
    cudaGetSymbolAddress((void**)&wlo, g_wplo);

    pack_w<<<2048, 256>>>(f_wih0, whi, wlo);
    pack_w<<<2048, 256>>>(b_wih0, whi + 524288, wlo + 524288);
    pack_w<<<4096, 256>>>(f_wih1, whi + 1048576, wlo + 1048576);
    pack_w<<<4096, 256>>>(b_wih1, whi + 2097152, wlo + 2097152);
    pack_x<<<512, 256>>>(x);

    dim3 g(G4 / 128, Tn);
    input_gemm_mma<<<g, 256, IN_SMEM>>>(whi, wlo, f_bih0, f_bhh0, 256, 0);
    input_gemm_mma<<<g, 256, IN_SMEM>>>(whi + 524288, wlo + 524288, b_bih0, b_bhh0, 256, 1);
    lstm_rec_mma<<<REC_CTAS, 256, REC_SMEM>>>(f_whh0, b_whh0, mask, out, 0);

    input_gemm_mma<<<g, 256, IN_SMEM>>>(whi + 1048576, wlo + 1048576, f_bih1, f_bhh1, 512, 0);
    input_gemm_mma<<<g, 256, IN_SMEM>>>(whi + 2097152, wlo + 2097152, b_bih1, b_bhh1, 512, 1);
    lstm_rec_mma<<<REC_CTAS, 256, REC_SMEM>>>(f_whh1, b_whh1, mask, out, 1);
}